// round 13
// baseline (speedup 1.0000x reference)
#include <cuda_runtime.h>
#include <math.h>
#include <cstdint>

#define B 2
#define NPROP 1000
#define NCLS 81
#define MASK_ELEMS (28*28*81)      // 63504 floats per proposal mask
#define MASK_V4 (MASK_ELEMS/4)     // 15876 float4
#define MAXI 100
#define NMS_THR 0.3f
#define MIN_CONF 0.5f
#define CAP 250                    // max candidates per class

// ---------------- scratch (device globals; no allocation allowed) ------------
__device__ float4 g_box[B * NPROP];
__device__ float  g_sc[B * NPROP];
__device__ short  g_cdv[B * NPROP];       // cid if keep0 else -1
__device__ short  g_cidv[B * NPROP];      // raw argmax cid
__device__ int    g_slot[B][MAXI];
__device__ int    g_kcount[B];

// ---------------- stage 1: warp-per-proposal prep (chip-wide) -----------------
__global__ __launch_bounds__(256) void prep_kernel(
        const float* __restrict__ rois,
        const float* __restrict__ probs,
        const float* __restrict__ deltas,
        const float* __restrict__ window) {
    int gw  = (blockIdx.x * blockDim.x + threadIdx.x) >> 5;   // global warp id
    int lid = threadIdx.x & 31;
    if (gw >= B * NPROP) return;

    const float* p = probs + (size_t)gw * NCLS;
    float bv = -1e30f; int bi = 0;
    #pragma unroll
    for (int o = 0; o < 96; o += 32) {
        int c = lid + o;
        if (c < NCLS) {
            float v = p[c];
            if (v > bv) { bv = v; bi = c; }
        }
    }
    // warp reduce: max value, tie -> min index (= first occurrence)
    #pragma unroll
    for (int o = 16; o > 0; o >>= 1) {
        float ov = __shfl_down_sync(0xFFFFFFFFu, bv, o);
        int   oi = __shfl_down_sync(0xFFFFFFFFu, bi, o);
        if (ov > bv || (ov == bv && oi < bi)) { bv = ov; bi = oi; }
    }
    bv = __shfl_sync(0xFFFFFFFFu, bv, 0);
    bi = __shfl_sync(0xFFFFFFFFu, bi, 0);

    if (lid == 0) {
        const float* r = rois + (size_t)gw * 4;
        float r0 = r[0], r1 = r[1], r2 = r[2], r3 = r[3];
        bool valid = (fabsf(r0) + fabsf(r1) + fabsf(r2) + fabsf(r3)) > 0.0f;

        const float* dl = deltas + ((size_t)gw * NCLS + bi) * 4;
        float dy = dl[0] * 0.1f, dx = dl[1] * 0.1f;
        float dh = dl[2] * 0.2f, dw = dl[3] * 0.2f;

        float h = r2 - r0, w = r3 - r1;
        float cy = r0 + 0.5f * h + dy * h;
        float cx = r1 + 0.5f * w + dx * w;
        h = h * expf(dh);
        w = w * expf(dw);
        float y1 = cy - 0.5f * h, x1 = cx - 0.5f * w;
        float y2 = cy + 0.5f * h, x2 = cx + 0.5f * w;

        float wy1 = window[0], wx1 = window[1], wy2 = window[2], wx2 = window[3];
        y1 = fminf(fmaxf(y1, wy1), wy2);
        x1 = fminf(fmaxf(x1, wx1), wx2);
        y2 = fminf(fmaxf(y2, wy1), wy2);
        x2 = fminf(fmaxf(x2, wx1), wx2);

        bool keep0 = valid && (bi > 0) && (bv >= MIN_CONF);
        g_box[gw]  = make_float4(y1, x1, y2, x2);
        g_sc[gw]   = bv;
        g_cidv[gw] = (short)bi;
        g_cdv[gw]  = keep0 ? (short)bi : (short)-1;
    }
}

// ---------------- stage 2-4: NMS + scan-topk + det (grid = B) -----------------
__global__ __launch_bounds__(1024) void detect_kernel(float* __restrict__ out) {
    __shared__ float4 s_box[NPROP];
    __shared__ float  s_sc[NPROP];
    __shared__ short  s_cd[NPROP];
    __shared__ unsigned char s_nms[NPROP];
    __shared__ short  s_cand[32][CAP];        // per-warp candidate lists
    __shared__ float  s_csc[32][CAP];         // matching scores (sorted together)
    __shared__ short  s_kidx[NPROP];
    __shared__ int    s_slot[MAXI];
    __shared__ int    s_wsum[32];
    __shared__ int    s_wpre[32];
    __shared__ int    s_K;

    int b   = blockIdx.x;
    int tid = threadIdx.x;
    int wid = tid / 32;
    int lid = tid % 32;

    if (tid < NPROP) {
        int idx = b * NPROP + tid;
        s_box[tid] = g_box[idx];
        s_sc[tid]  = g_sc[idx];
        s_cd[tid]  = g_cdv[idx];
        s_nms[tid] = 0;
    }
    __syncthreads();

    // ---- per-class greedy NMS (one class per warp, strided) ----
    for (int c = 1 + wid; c < NCLS; c += 32) {
        // ballot compaction: ascending-index candidate list for class c
        int k = 0;
        for (int base = 0; base < NPROP; base += 32) {
            int i = base + lid;
            bool hit = (i < NPROP) && (s_cd[i] == (short)c);
            unsigned m = __ballot_sync(0xFFFFFFFFu, hit);
            if (hit) {
                int pos = k + __popc(m & ((1u << lid) - 1u));
                if (pos < CAP) {
                    s_cand[wid][pos] = (short)i;
                    s_csc[wid][pos]  = s_sc[i];
                }
            }
            k += __popc(m);
        }
        if (k > CAP) k = CAP;
        __syncwarp();

        if (lid == 0 && k > 0) {
            // insertion sort by (score desc, idx asc); stable on equal scores.
            for (int a = 1; a < k; a++) {
                short ci = s_cand[wid][a];
                float si = s_csc[wid][a];
                int t = a - 1;
                while (t >= 0) {
                    if (s_csc[wid][t] >= si) break;
                    s_cand[wid][t + 1] = s_cand[wid][t];
                    s_csc[wid][t + 1]  = s_csc[wid][t];
                    t--;
                }
                s_cand[wid][t + 1] = ci;
                s_csc[wid][t + 1]  = si;
            }
            // linear greedy over sorted order
            float4 kb[MAXI]; int nk = 0;
            for (int a = 0; a < k && nk < MAXI; a++) {
                int i = s_cand[wid][a];
                float4 bx = s_box[i];
                float area = (bx.z - bx.x) * (bx.w - bx.y);
                bool sup = false;
                for (int t = 0; t < nk; t++) {
                    float iy1 = fmaxf(kb[t].x, bx.x), ix1 = fmaxf(kb[t].y, bx.y);
                    float iy2 = fminf(kb[t].z, bx.z), ix2 = fminf(kb[t].w, bx.w);
                    float inter = fmaxf(iy2 - iy1, 0.0f) * fmaxf(ix2 - ix1, 0.0f);
                    float ka = (kb[t].z - kb[t].x) * (kb[t].w - kb[t].y);
                    float iou = inter / (ka + area - inter + 1e-8f);
                    if (iou > NMS_THR) { sup = true; break; }
                }
                if (!sup) { kb[nk] = bx; nk++; s_nms[i] = 1; }
            }
        }
        __syncwarp();
    }
    __syncthreads();

    // ---- block scan over keep flags ----
    bool f = (tid < NPROP) && s_nms[tid];
    unsigned bal = __ballot_sync(0xFFFFFFFFu, f);
    int before_in_warp = __popc(bal & ((1u << lid) - 1u));
    if (lid == 0) s_wsum[wid] = __popc(bal);
    __syncthreads();
    if (wid == 0) {
        int v = s_wsum[lid];
        int inc = v;
        #pragma unroll
        for (int o = 1; o < 32; o <<= 1) {
            int n = __shfl_up_sync(0xFFFFFFFFu, inc, o);
            if (lid >= o) inc += n;
        }
        s_wpre[lid] = inc - v;
        if (lid == 31) s_K = inc;
    }
    __syncthreads();
    int prefix = s_wpre[wid] + before_in_warp;
    int K = s_K;
    int kcc = min(K, MAXI);

    if (f) s_kidx[prefix] = (short)tid;
    if (tid < NPROP && !f) {
        int slot = kcc + (tid - prefix);
        if (slot < MAXI) s_slot[slot] = tid;
    }
    __syncthreads();

    for (int t = tid; t < K; t += 1024) {
        int i = s_kidx[t];
        float si = s_sc[i];
        int r = 0;
        for (int u = 0; u < K; u++) {
            int iu = s_kidx[u];
            float su = s_sc[iu];
            r += (su > si) || (su == si && iu < i);
        }
        if (r < MAXI) s_slot[r] = i;
    }
    __syncthreads();

    if (tid < MAXI) {
        g_slot[b][tid] = s_slot[tid];
        float* o = out + ((size_t)b * MAXI + tid) * 6;
        if (tid < kcc) {
            int i = s_slot[tid];
            float4 bx = s_box[i];
            o[0] = bx.x; o[1] = bx.y; o[2] = bx.z; o[3] = bx.w;
            o[4] = (float)s_cd[i];       // kept => keep0 true => cd == cid
            o[5] = s_sc[i];
        } else {
            o[0] = 0.f; o[1] = 0.f; o[2] = 0.f; o[3] = 0.f; o[4] = 0.f; o[5] = 0.f;
        }
    }
    if (tid == 0) g_kcount[b] = kcc;
}

// ---------------- stage 5: 5-D broadcast mask write via TMA bulk stores -------
// Champion config (833.7us total): CHUNK=16KB, dual buffers, bulk_group stores.
// out[b,i,j,:] = (i < kcount[b]) ? masks[b, slot[j], :] : 0
#define CHUNK_V4 1024          // float4 per block-chunk (16 KB)
#define NCHUNK   16            // ceil(15876 / 1024)

__device__ __forceinline__ uint32_t smem_u32(const void* p) {
    uint32_t a;
    asm("{ .reg .u64 t; cvta.to.shared.u64 t, %1; cvt.u32.u64 %0, t; }"
        : "=r"(a) : "l"(p));
    return a;
}

__global__ __launch_bounds__(256) void mask5d_tma_kernel(
        const float* __restrict__ masks, float* __restrict__ out) {
    __shared__ alignas(128) float4 s_data[CHUNK_V4];
    __shared__ alignas(128) float4 s_zero[CHUNK_V4];

    int b = blockIdx.z;
    int j = blockIdx.y;
    int chunk0 = blockIdx.x * CHUNK_V4;
    int n_v4 = MASK_V4 - chunk0; if (n_v4 > CHUNK_V4) n_v4 = CHUNK_V4;

    int kc   = g_kcount[b];
    int slot = g_slot[b][j];

    const float4* src = (const float4*)(masks + (size_t)(b * NPROP + slot) * MASK_ELEMS)
                        + chunk0;
    const float4 z = make_float4(0.f, 0.f, 0.f, 0.f);
    for (int t = threadIdx.x; t < n_v4; t += 256) {
        s_data[t] = __ldcs(&src[t]);     // streaming: read-once source
        s_zero[t] = z;
    }
    __syncthreads();
    asm volatile("fence.proxy.async.shared::cta;" ::: "memory");

    if (threadIdx.x == 0) {
        uint32_t sa_data = smem_u32(s_data);
        uint32_t sa_zero = smem_u32(s_zero);
        char* dst = (char*)((float4*)(out + (size_t)B * MAXI * 6)
                    + ((size_t)(b * MAXI) * MAXI + j) * MASK_V4 + chunk0);
        const size_t istride = (size_t)MAXI * MASK_V4 * 16;
        const int bytes = n_v4 * 16;

        int i = 0;
        for (; i < kc; i++) {
            asm volatile(
                "cp.async.bulk.global.shared::cta.bulk_group [%0], [%1], %2;"
                :: "l"(dst), "r"(sa_data), "r"(bytes) : "memory");
            dst += istride;
        }
        for (; i < MAXI; i++) {
            asm volatile(
                "cp.async.bulk.global.shared::cta.bulk_group [%0], [%1], %2;"
                :: "l"(dst), "r"(sa_zero), "r"(bytes) : "memory");
            dst += istride;
        }
        asm volatile("cp.async.bulk.commit_group;" ::: "memory");
        asm volatile("cp.async.bulk.wait_group 0;" ::: "memory");
    }
    __syncthreads();   // SMEM must stay alive until TMA reads complete
}

// ---------------- 4-D fallback (defensive) ------------------------------------
__global__ void mask4d_kernel(const float* __restrict__ masks, float* __restrict__ out) {
    long long e = (long long)blockIdx.x * blockDim.x + threadIdx.x;
    long long total = (long long)B * MAXI * MASK_V4;
    if (e >= total) return;
    int row = (int)(e / MASK_V4);
    int w   = (int)(e % MASK_V4);
    int b = row / MAXI, s = row % MAXI;
    float4 v = make_float4(0.f, 0.f, 0.f, 0.f);
    if (s < g_kcount[b]) {
        int i = g_slot[b][s];
        const float4* src = (const float4*)(masks + (size_t)(b * NPROP + i) * MASK_ELEMS);
        v = src[w];
    }
    float4* dst = (float4*)(out + (size_t)B * MAXI * 6);
    dst[e] = v;
}

// ---------------- launch ------------------------------------------------------
extern "C" void kernel_launch(void* const* d_in, const int* in_sizes, int n_in,
                              void* d_out, int out_size) {
    const float* rois   = (const float*)d_in[0];
    const float* probs  = (const float*)d_in[1];
    const float* deltas = (const float*)d_in[2];
    const float* masks  = (const float*)d_in[3];
    const float* window = (const float*)d_in[4];
    float* out = (float*)d_out;

    int warps = B * NPROP;                       // one warp per proposal
    int pblocks = (warps * 32 + 255) / 256;      // 250 blocks
    prep_kernel<<<pblocks, 256>>>(rois, probs, deltas, window);
    detect_kernel<<<B, 1024>>>(out);

    long long det_elems  = (long long)B * MAXI * 6;
    long long mask_elems = (long long)out_size - det_elems;
    long long rows = mask_elems / MASK_ELEMS;

    if (rows >= (long long)B * MAXI * MAXI) {
        dim3 grid(NCHUNK, MAXI, B);
        mask5d_tma_kernel<<<grid, 256>>>(masks, out);
    } else {
        long long total = (long long)B * MAXI * MASK_V4;
        int gridn = (int)((total + 255) / 256);
        mask4d_kernel<<<gridn, 256>>>(masks, out);
    }
}

// round 14
// speedup vs baseline: 1.0115x; 1.0115x over previous
#include <cuda_runtime.h>
#include <math.h>
#include <cstdint>

#define B 2
#define NPROP 1000
#define NCLS 81
#define MASK_ELEMS (28*28*81)      // 63504 floats per proposal mask
#define MASK_V4 (MASK_ELEMS/4)     // 15876 float4
#define MAXI 100
#define NMS_THR 0.3f
#define MIN_CONF 0.5f
#define CAP 250                    // max candidates per class

// ---------------- scratch (device globals; no allocation allowed) ------------
__device__ float4 g_box[B * NPROP];
__device__ float  g_sc[B * NPROP];
__device__ short  g_cidv[B * NPROP];
__device__ short  g_cdv[B * NPROP];       // cid if keep0 else -1
__device__ int    g_slot[B][MAXI];
__device__ int    g_kcount[B];

// ---------------- stage 1: warp-per-proposal prep (chip-wide) -----------------
__global__ __launch_bounds__(256) void prep_kernel(
        const float* __restrict__ rois,
        const float* __restrict__ probs,
        const float* __restrict__ deltas,
        const float* __restrict__ window) {
    int gw  = (blockIdx.x * blockDim.x + threadIdx.x) >> 5;   // global warp id
    int lid = threadIdx.x & 31;
    if (gw >= B * NPROP) return;

    const float* p = probs + (size_t)gw * NCLS;
    float bv = -1e30f; int bi = 0;
    #pragma unroll
    for (int o = 0; o < 96; o += 32) {
        int c = lid + o;
        if (c < NCLS) {
            float v = p[c];
            if (v > bv) { bv = v; bi = c; }
        }
    }
    // warp reduce: max value, tie -> min index (= first occurrence)
    #pragma unroll
    for (int o = 16; o > 0; o >>= 1) {
        float ov = __shfl_down_sync(0xFFFFFFFFu, bv, o);
        int   oi = __shfl_down_sync(0xFFFFFFFFu, bi, o);
        if (ov > bv || (ov == bv && oi < bi)) { bv = ov; bi = oi; }
    }
    bv = __shfl_sync(0xFFFFFFFFu, bv, 0);
    bi = __shfl_sync(0xFFFFFFFFu, bi, 0);

    if (lid == 0) {
        const float* r = rois + (size_t)gw * 4;
        float r0 = r[0], r1 = r[1], r2 = r[2], r3 = r[3];
        bool valid = (fabsf(r0) + fabsf(r1) + fabsf(r2) + fabsf(r3)) > 0.0f;

        const float* dl = deltas + ((size_t)gw * NCLS + bi) * 4;
        float dy = dl[0] * 0.1f, dx = dl[1] * 0.1f;
        float dh = dl[2] * 0.2f, dw = dl[3] * 0.2f;

        float h = r2 - r0, w = r3 - r1;
        float cy = r0 + 0.5f * h + dy * h;
        float cx = r1 + 0.5f * w + dx * w;
        h = h * expf(dh);
        w = w * expf(dw);
        float y1 = cy - 0.5f * h, x1 = cx - 0.5f * w;
        float y2 = cy + 0.5f * h, x2 = cx + 0.5f * w;

        float wy1 = window[0], wx1 = window[1], wy2 = window[2], wx2 = window[3];
        y1 = fminf(fmaxf(y1, wy1), wy2);
        x1 = fminf(fmaxf(x1, wx1), wx2);
        y2 = fminf(fmaxf(y2, wy1), wy2);
        x2 = fminf(fmaxf(x2, wx1), wx2);

        bool keep0 = valid && (bi > 0) && (bv >= MIN_CONF);
        g_box[gw]  = make_float4(y1, x1, y2, x2);
        g_sc[gw]   = bv;
        g_cidv[gw] = (short)bi;
        g_cdv[gw]  = keep0 ? (short)bi : (short)-1;
    }
}

// ---------------- stage 2-4: NMS + scan-topk + det (grid = B) -----------------
__global__ __launch_bounds__(1024) void detect_kernel(float* __restrict__ out) {
    __shared__ float4 s_box[NPROP];
    __shared__ float  s_sc[NPROP];
    __shared__ short  s_cd[NPROP];
    __shared__ short  s_cid[NPROP];
    __shared__ unsigned char s_nms[NPROP];
    __shared__ short  s_cand[32][CAP];        // sorted candidate lists per warp
    __shared__ short  s_kidx[NPROP];
    __shared__ int    s_slot[MAXI];
    __shared__ int    s_wsum[32];
    __shared__ int    s_wpre[32];
    __shared__ int    s_K;

    int b   = blockIdx.x;
    int tid = threadIdx.x;
    int wid = tid / 32;
    int lid = tid % 32;

    if (tid < NPROP) {
        int idx = b * NPROP + tid;
        s_box[tid] = g_box[idx];
        s_sc[tid]  = g_sc[idx];
        s_cid[tid] = g_cidv[idx];
        s_cd[tid]  = g_cdv[idx];
        s_nms[tid] = 0;
    }
    __syncthreads();

    // ---- per-class greedy NMS (one class per warp, strided) ----
    for (int c = 1 + wid; c < NCLS; c += 32) {
        // ballot compaction: ascending-index candidate list for class c
        int k = 0;
        for (int base = 0; base < NPROP; base += 32) {
            int i = base + lid;
            bool hit = (i < NPROP) && (s_cd[i] == (short)c);
            unsigned m = __ballot_sync(0xFFFFFFFFu, hit);
            if (hit) {
                int pos = k + __popc(m & ((1u << lid) - 1u));
                if (pos < CAP) s_cand[wid][pos] = (short)i;
            }
            k += __popc(m);
        }
        if (k > CAP) k = CAP;
        __syncwarp();

        if (lid == 0 && k > 0) {
            // insertion sort by (score desc, idx asc); input ascending-index,
            // stable insertion keeps first-occurrence tie-break.
            for (int a = 1; a < k; a++) {
                short ci = s_cand[wid][a];
                float si = s_sc[ci];
                int t = a - 1;
                while (t >= 0) {
                    short ct = s_cand[wid][t];
                    if (s_sc[ct] >= si) break;
                    s_cand[wid][t + 1] = ct;
                    t--;
                }
                s_cand[wid][t + 1] = ci;
            }
            // linear greedy over sorted order
            float4 kb[MAXI]; int nk = 0;
            for (int a = 0; a < k && nk < MAXI; a++) {
                int i = s_cand[wid][a];
                float4 bx = s_box[i];
                float area = (bx.z - bx.x) * (bx.w - bx.y);
                bool sup = false;
                for (int t = 0; t < nk; t++) {
                    float iy1 = fmaxf(kb[t].x, bx.x), ix1 = fmaxf(kb[t].y, bx.y);
                    float iy2 = fminf(kb[t].z, bx.z), ix2 = fminf(kb[t].w, bx.w);
                    float inter = fmaxf(iy2 - iy1, 0.0f) * fmaxf(ix2 - ix1, 0.0f);
                    float ka = (kb[t].z - kb[t].x) * (kb[t].w - kb[t].y);
                    float iou = inter / (ka + area - inter + 1e-8f);
                    if (iou > NMS_THR) { sup = true; break; }
                }
                if (!sup) { kb[nk] = bx; nk++; s_nms[i] = 1; }
            }
        }
        __syncwarp();
    }
    __syncthreads();

    // ---- block scan over keep flags ----
    bool f = (tid < NPROP) && s_nms[tid];
    unsigned bal = __ballot_sync(0xFFFFFFFFu, f);
    int before_in_warp = __popc(bal & ((1u << lid) - 1u));
    if (lid == 0) s_wsum[wid] = __popc(bal);
    __syncthreads();
    if (wid == 0) {
        int v = s_wsum[lid];
        int inc = v;
        #pragma unroll
        for (int o = 1; o < 32; o <<= 1) {
            int n = __shfl_up_sync(0xFFFFFFFFu, inc, o);
            if (lid >= o) inc += n;
        }
        s_wpre[lid] = inc - v;
        if (lid == 31) s_K = inc;
    }
    __syncthreads();
    int prefix = s_wpre[wid] + before_in_warp;
    int K = s_K;
    int kcc = min(K, MAXI);

    if (f) s_kidx[prefix] = (short)tid;
    if (tid < NPROP && !f) {
        int slot = kcc + (tid - prefix);
        if (slot < MAXI) s_slot[slot] = tid;
    }
    __syncthreads();

    for (int t = tid; t < K; t += 1024) {
        int i = s_kidx[t];
        float si = s_sc[i];
        int r = 0;
        for (int u = 0; u < K; u++) {
            int iu = s_kidx[u];
            float su = s_sc[iu];
            r += (su > si) || (su == si && iu < i);
        }
        if (r < MAXI) s_slot[r] = i;
    }
    __syncthreads();

    if (tid < MAXI) {
        g_slot[b][tid] = s_slot[tid];
        float* o = out + ((size_t)b * MAXI + tid) * 6;
        if (tid < kcc) {
            int i = s_slot[tid];
            float4 bx = s_box[i];
            o[0] = bx.x; o[1] = bx.y; o[2] = bx.z; o[3] = bx.w;
            o[4] = (float)s_cid[i];
            o[5] = s_sc[i];
        } else {
            o[0] = 0.f; o[1] = 0.f; o[2] = 0.f; o[3] = 0.f; o[4] = 0.f; o[5] = 0.f;
        }
    }
    if (tid == 0) g_kcount[b] = kcc;
}

// ---------------- stage 5: 5-D broadcast mask write via TMA bulk stores -------
// Champion config (833.7us total): CHUNK=16KB, dual buffers, bulk_group stores.
// out[b,i,j,:] = (i < kcount[b]) ? masks[b, slot[j], :] : 0
#define CHUNK_V4 1024          // float4 per block-chunk (16 KB)
#define NCHUNK   16            // ceil(15876 / 1024)

__device__ __forceinline__ uint32_t smem_u32(const void* p) {
    uint32_t a;
    asm("{ .reg .u64 t; cvta.to.shared.u64 t, %1; cvt.u32.u64 %0, t; }"
        : "=r"(a) : "l"(p));
    return a;
}

__global__ __launch_bounds__(256) void mask5d_tma_kernel(
        const float* __restrict__ masks, float* __restrict__ out) {
    __shared__ alignas(128) float4 s_data[CHUNK_V4];
    __shared__ alignas(128) float4 s_zero[CHUNK_V4];

    int b = blockIdx.z;
    int j = blockIdx.y;
    int chunk0 = blockIdx.x * CHUNK_V4;
    int n_v4 = MASK_V4 - chunk0; if (n_v4 > CHUNK_V4) n_v4 = CHUNK_V4;

    int kc   = g_kcount[b];
    int slot = g_slot[b][j];

    const float4* src = (const float4*)(masks + (size_t)(b * NPROP + slot) * MASK_ELEMS)
                        + chunk0;
    const float4 z = make_float4(0.f, 0.f, 0.f, 0.f);
    for (int t = threadIdx.x; t < n_v4; t += 256) {
        s_data[t] = __ldg(&src[t]);
        s_zero[t] = z;
    }
    __syncthreads();
    asm volatile("fence.proxy.async.shared::cta;" ::: "memory");

    if (threadIdx.x == 0) {
        uint32_t sa_data = smem_u32(s_data);
        uint32_t sa_zero = smem_u32(s_zero);
        char* dst = (char*)((float4*)(out + (size_t)B * MAXI * 6)
                    + ((size_t)(b * MAXI) * MAXI + j) * MASK_V4 + chunk0);
        const size_t istride = (size_t)MAXI * MASK_V4 * 16;
        const int bytes = n_v4 * 16;

        int i = 0;
        for (; i < kc; i++) {
            asm volatile(
                "cp.async.bulk.global.shared::cta.bulk_group [%0], [%1], %2;"
                :: "l"(dst), "r"(sa_data), "r"(bytes) : "memory");
            dst += istride;
        }
        for (; i < MAXI; i++) {
            asm volatile(
                "cp.async.bulk.global.shared::cta.bulk_group [%0], [%1], %2;"
                :: "l"(dst), "r"(sa_zero), "r"(bytes) : "memory");
            dst += istride;
        }
        asm volatile("cp.async.bulk.commit_group;" ::: "memory");
        asm volatile("cp.async.bulk.wait_group 0;" ::: "memory");
    }
    __syncthreads();   // SMEM must stay alive until TMA reads complete
}

// ---------------- 4-D fallback (defensive) ------------------------------------
__global__ void mask4d_kernel(const float* __restrict__ masks, float* __restrict__ out) {
    long long e = (long long)blockIdx.x * blockDim.x + threadIdx.x;
    long long total = (long long)B * MAXI * MASK_V4;
    if (e >= total) return;
    int row = (int)(e / MASK_V4);
    int w   = (int)(e % MASK_V4);
    int b = row / MAXI, s = row % MAXI;
    float4 v = make_float4(0.f, 0.f, 0.f, 0.f);
    if (s < g_kcount[b]) {
        int i = g_slot[b][s];
        const float4* src = (const float4*)(masks + (size_t)(b * NPROP + i) * MASK_ELEMS);
        v = src[w];
    }
    float4* dst = (float4*)(out + (size_t)B * MAXI * 6);
    dst[e] = v;
}

// ---------------- launch ------------------------------------------------------
extern "C" void kernel_launch(void* const* d_in, const int* in_sizes, int n_in,
                              void* d_out, int out_size) {
    const float* rois   = (const float*)d_in[0];
    const float* probs  = (const float*)d_in[1];
    const float* deltas = (const float*)d_in[2];
    const float* masks  = (const float*)d_in[3];
    const float* window = (const float*)d_in[4];
    float* out = (float*)d_out;

    int warps = B * NPROP;                       // one warp per proposal
    int pblocks = (warps * 32 + 255) / 256;      // 250 blocks
    prep_kernel<<<pblocks, 256>>>(rois, probs, deltas, window);
    detect_kernel<<<B, 1024>>>(out);

    long long det_elems  = (long long)B * MAXI * 6;
    long long mask_elems = (long long)out_size - det_elems;
    long long rows = mask_elems / MASK_ELEMS;

    if (rows >= (long long)B * MAXI * MAXI) {
        dim3 grid(NCHUNK, MAXI, B);
        mask5d_tma_kernel<<<grid, 256>>>(masks, out);
    } else {
        long long total = (long long)B * MAXI * MASK_V4;
        int gridn = (int)((total + 255) / 256);
        mask4d_kernel<<<gridn, 256>>>(masks, out);
    }
}